// round 16
// baseline (speedup 1.0000x reference)
#include <cuda_runtime.h>

// ColorQuantizer: out[pix] = PALETTE[argmin_j | relu(x@W1+b1)@W2+b2 - c_j |^2]
// Straight-through output == hard palette lookup; softmax/sqrt/cdist drop out.
//
// R14 (resubmit after infra failure): issue-slot trim. The fully-unrolled MLP
// issued 224 scalar LDCU/warp (7 consts x 32 units). Interleave the constant
// layout as float4 pairs so each unit is two ld.const.v4 -> LDCU.128 (UR-dest):
// 64 loads, -160 issue slots/warp (~-6.6%). Everything else identical to R13
// (UR-operand rt1 FFMA, sparse shifted-palette scores, 8 px/thread, tournament
// argmin, 3-node graph).

#define HW    262144u            // 512*512
#define NTHR8 (32u * HW / 8u)    // 1,048,576 threads, 8 px each

#define PV(v) ((float)(v) / 255.0f * 2.0f - 1.0f)
#define P3(a,b,c) {PV(a), PV(b), PV(c)}
static __device__ constexpr float PAL[16][3] = {
    P3(0,0,0),       P3(255,255,255), P3(255,0,0),     P3(0,255,0),
    P3(0,0,255),     P3(255,255,0),   P3(255,0,255),   P3(0,255,255),
    P3(128,128,128), P3(128,0,0),     P3(0,128,0),     P3(0,0,128),
    P3(128,128,0),   P3(128,0,128),   P3(0,128,128),   P3(192,192,192)
};

// Interleaved constant block, float4-typed for ld.const.v4:
//  [2k]   = {W1[0][k], W1[1][k], W1[2][k], b1[k]}
//  [2k+1] = {W2[k][0], W2[k][1], W2[k][2], 0}
//  [64]   = {b2[0], b2[1], b2[2], 0}
__constant__ float4 cPack[65];
__device__   float  g_stage[260];

__global__ void gather_kernel(const float* __restrict__ W1, const float* __restrict__ b1,
                              const float* __restrict__ W2, const float* __restrict__ b2) {
    int i = threadIdx.x;                       // 260 threads
    float v = 0.0f;
    if (i < 256) {
        int k = i >> 3, c = i & 7;
        if (c < 3)       v = W1[c * 32 + k];
        else if (c == 3) v = b1[k];
        else if (c < 7)  v = W2[k * 3 + (c - 4)];
        else             v = 0.0f;
    } else if (i < 259) {
        v = b2[i - 256];
    }
    if (i < 260) g_stage[i] = v;
}

// Tournament node: keeps (score, idx) of the smaller score; exact tie keeps
// the LEFT (lower-index) argument -> first-index-wins, matching the reference.
#define TMIN(sa, ia, sb, ib, so, io)  do { \
    bool _p = (sb) < (sa);                  \
    so = _p ? (sb) : (sa);                  \
    io = _p ? (ib) : (ia);                  \
} while (0)

__global__ __launch_bounds__(256) void cq_kernel(const float* __restrict__ x,
                                                 float* __restrict__ out) {
    __shared__ float4 spal4[16];   // palette gather LUT (per-lane dynamic index)

    int tid = threadIdx.x;
    if (tid < 16)
        spal4[tid] = make_float4(PAL[tid][0], PAL[tid][1], PAL[tid][2], 0.0f);
    __syncthreads();

    unsigned q = blockIdx.x * 256u + tid;      // 8-px group index
    unsigned b = q >> 15;                      // batch = q / (HW/8)
    unsigned r = (q & 32767u) << 3;            // pixel offset within plane

    const float* base = x + (size_t)b * 3 * HW + r;
    float X0[8], X1[8], X2[8];
    {
        float4 t;
        t = reinterpret_cast<const float4*>(base)[0];
        X0[0]=t.x; X0[1]=t.y; X0[2]=t.z; X0[3]=t.w;
        t = reinterpret_cast<const float4*>(base)[1];
        X0[4]=t.x; X0[5]=t.y; X0[6]=t.z; X0[7]=t.w;
        t = reinterpret_cast<const float4*>(base + HW)[0];
        X1[0]=t.x; X1[1]=t.y; X1[2]=t.z; X1[3]=t.w;
        t = reinterpret_cast<const float4*>(base + HW)[1];
        X1[4]=t.x; X1[5]=t.y; X1[6]=t.z; X1[7]=t.w;
        t = reinterpret_cast<const float4*>(base + 2 * HW)[0];
        X2[0]=t.x; X2[1]=t.y; X2[2]=t.z; X2[3]=t.w;
        t = reinterpret_cast<const float4*>(base + 2 * HW)[1];
        X2[4]=t.x; X2[5]=t.y; X2[6]=t.z; X2[7]=t.w;
    }

    float4 cb2 = cPack[64];
    float p0[8], p1[8], p2[8];
    #pragma unroll
    for (int i = 0; i < 8; i++) { p0[i] = cb2.x; p1[i] = cb2.y; p2[i] = cb2.z; }

    // MLP: per unit, two float4 constant loads (LDCU.128) -> UR operands -> rt1.
    #pragma unroll
    for (int k = 0; k < 32; k++) {
        float4 wa = cPack[2 * k];        // {wx, wy, wz, b1}
        float4 wb = cPack[2 * k + 1];    // {u0, u1, u2, 0}
        #pragma unroll
        for (int i = 0; i < 8; i++) {
            float a = fmaf(X0[i], wa.x, fmaf(X1[i], wa.y, fmaf(X2[i], wa.z, wa.w)));
            float h = fmaxf(a, 0.0f);          // FMNMX: alu pipe
            p0[i] = fmaf(h, wb.x, p0[i]);
            p1[i] = fmaf(h, wb.y, p1[i]);
            p2[i] = fmaf(h, wb.z, p2[i]);
        }
    }

    float r0[8], r1[8], r2[8];
    #pragma unroll
    for (int i = 0; i < 8; i++) {
        float q0 = p0[i], q1 = p1[i], q2 = p2[i];

        // Shifted-palette scores: s_j = -2 q.(C_j+1) + |C_j|^2 (argmin-preserving;
        // zero-byte channels fold away; s_0 == 3.0 exactly). All 16 independent.
        float s[16];
        s[0] = 3.0f;
        #pragma unroll
        for (int j = 1; j < 16; j++) {
            const float m0  = -2.0f * (PAL[j][0] + 1.0f);
            const float m1  = -2.0f * (PAL[j][1] + 1.0f);
            const float m2  = -2.0f * (PAL[j][2] + 1.0f);
            const float csq = PAL[j][0] * PAL[j][0] + PAL[j][1] * PAL[j][1]
                            + PAL[j][2] * PAL[j][2];
            float v = csq;
            if (m2 != 0.0f) v = fmaf(q2, m2, v);
            if (m1 != 0.0f) v = fmaf(q1, m1, v);
            if (m0 != 0.0f) v = fmaf(q0, m0, v);
            s[j] = v;
        }

        // Balanced tournament: 8+4+2+1 compares, critical path 4.
        float ts[8]; int ti[8];
        #pragma unroll
        for (int m = 0; m < 8; m++)
            TMIN(s[2 * m], 2 * m, s[2 * m + 1], 2 * m + 1, ts[m], ti[m]);
        float us[4]; int ui[4];
        #pragma unroll
        for (int m = 0; m < 4; m++)
            TMIN(ts[2 * m], ti[2 * m], ts[2 * m + 1], ti[2 * m + 1], us[m], ui[m]);
        float vs0, vs1; int vi0, vi1;
        TMIN(us[0], ui[0], us[1], ui[1], vs0, vi0);
        TMIN(us[2], ui[2], us[3], ui[3], vs1, vi1);
        float fs; int bi;
        TMIN(vs0, vi0, vs1, vi1, fs, bi);
        (void)fs;

        float4 col = spal4[bi];
        r0[i] = col.x; r1[i] = col.y; r2[i] = col.z;

        // Retire first half's results early to cap register pressure.
        if (i == 3) {
            float* obase = out + (size_t)b * 3 * HW + r;
            reinterpret_cast<float4*>(obase)[0]          = make_float4(r0[0], r0[1], r0[2], r0[3]);
            reinterpret_cast<float4*>(obase + HW)[0]     = make_float4(r1[0], r1[1], r1[2], r1[3]);
            reinterpret_cast<float4*>(obase + 2 * HW)[0] = make_float4(r2[0], r2[1], r2[2], r2[3]);
        }
    }

    float* obase = out + (size_t)b * 3 * HW + r;
    reinterpret_cast<float4*>(obase)[1]          = make_float4(r0[4], r0[5], r0[6], r0[7]);
    reinterpret_cast<float4*>(obase + HW)[1]     = make_float4(r1[4], r1[5], r1[6], r1[7]);
    reinterpret_cast<float4*>(obase + 2 * HW)[1] = make_float4(r2[4], r2[5], r2[6], r2[7]);
}

extern "C" void kernel_launch(void* const* d_in, const int* in_sizes, int n_in,
                              void* d_out, int out_size) {
    const float* x  = (const float*)d_in[0];
    float* out = (float*)d_out;

    gather_kernel<<<1, 260>>>((const float*)d_in[1], (const float*)d_in[2],
                              (const float*)d_in[3], (const float*)d_in[4]);

    void* stage_ptr = nullptr;
    cudaGetSymbolAddress(&stage_ptr, g_stage);   // address query only, no stream op
    cudaMemcpyToSymbolAsync(cPack, stage_ptr, 260 * sizeof(float), 0,
                            cudaMemcpyDeviceToDevice, 0);

    cq_kernel<<<NTHR8 / 256, 256>>>(x, out);
}